// round 11
// baseline (speedup 1.0000x reference)
#include <cuda_runtime.h>

// out = (Q K^T) V == Q (K^T V).  B=1, H=16, S=4096, D=64, fp32.
// Phase A: partial M_hc = K_chunk^T V_chunk   (f32x2, dup-K, natural layout)
// Phase B: M[h] = sum_c partial               (float4 coalesced)
// Phase C: out = Q @ M                        (f32x2, dup-Q, natural layout)

#define NH      16
#define SS      4096
#define DD      64
#define CHUNKS  64
#define CHUNK_S 64           // one 64x64 tile per phase-A block

__device__ float g_partial[NH * CHUNKS * DD * DD];  // 16.8 MB (L2-resident)
__device__ float g_M[NH * DD * DD];                 // 256 KB, M[h][d*64+j]

// packed fp32x2 FMA: d.lo += a.lo*b.lo ; d.hi += a.hi*b.hi
#define FFMA2(d, a, b) \
    asm("fma.rn.f32x2 %0, %1, %2, %0;" : "+l"(d) : "l"(a), "l"(b))

__device__ __forceinline__ unsigned long long dup2(float f) {
    unsigned long long r;
    asm("mov.b64 %0, {%1, %1};" : "=l"(r) : "f"(f));
    return r;
}

// ---------------------------------------------------------------------------
// Phase A: per-(head, chunk) partial K^T V.  Grid 1024 -> ~5 CTAs/SM.
// 256 threads as 16x16; thread (ty,tx) owns M[ty*4..+3][tx*4..+3].
// K read as broadcast LDS.128, V conflict-free LDS.128; packed math via
// register duplication of K (alu pipe, nearly free).
// ---------------------------------------------------------------------------
__global__ __launch_bounds__(256) void ktv_partial_kernel(
    const float* __restrict__ kg, const float* __restrict__ vg)
{
    __shared__ float ks[DD * DD];   // 16 KB
    __shared__ float vs[DD * DD];   // 16 KB

    const int bx    = blockIdx.x;
    const int h     = bx >> 6;
    const int chunk = bx & 63;
    const int tid   = threadIdx.x;
    const int ty    = tid >> 4;
    const int tx    = tid & 15;

    const float4* Kg = (const float4*)(kg + (h * SS + chunk * CHUNK_S) * DD);
    const float4* Vg = (const float4*)(vg + (h * SS + chunk * CHUNK_S) * DD);
    float4* ks4 = (float4*)ks;
    float4* vs4 = (float4*)vs;

    // Stage the 64x64 K and V tiles (coalesced float4).
    #pragma unroll
    for (int i = 0; i < 4; ++i) {
        int idx = tid + i * 256;
        ks4[idx] = Kg[idx];
        vs4[idx] = Vg[idx];
    }
    __syncthreads();

    unsigned long long acc[4][2];
    #pragma unroll
    for (int r = 0; r < 4; ++r) { acc[r][0] = 0ULL; acc[r][1] = 0ULL; }

    #pragma unroll 8
    for (int s = 0; s < 64; ++s) {
        float4     kk = *(const float4*)&ks[s * DD + ty * 4];     // broadcast
        ulonglong2 vv = *(const ulonglong2*)&vs[s * DD + tx * 4]; // conflict-free
        unsigned long long kd0 = dup2(kk.x);
        unsigned long long kd1 = dup2(kk.y);
        unsigned long long kd2 = dup2(kk.z);
        unsigned long long kd3 = dup2(kk.w);
        FFMA2(acc[0][0], kd0, vv.x); FFMA2(acc[0][1], kd0, vv.y);
        FFMA2(acc[1][0], kd1, vv.x); FFMA2(acc[1][1], kd1, vv.y);
        FFMA2(acc[2][0], kd2, vv.x); FFMA2(acc[2][1], kd2, vv.y);
        FFMA2(acc[3][0], kd3, vv.x); FFMA2(acc[3][1], kd3, vv.y);
    }

    float* P = g_partial + (h * CHUNKS + chunk) * DD * DD;
    #pragma unroll
    for (int r = 0; r < 4; ++r) {
        *(ulonglong2*)&P[(ty * 4 + r) * DD + tx * 4] =
            make_ulonglong2(acc[r][0], acc[r][1]);
    }
}

// ---------------------------------------------------------------------------
// Phase B: reduce 64 chunk-partials per head into M (float4 everywhere).
// 16384 threads, each owns one float4 of M.
// ---------------------------------------------------------------------------
__global__ __launch_bounds__(256) void reduce_kernel()
{
    int o4 = blockIdx.x * 256 + threadIdx.x;     // grid 64 -> 16384 float4s
    int h  = o4 >> 10;                           // 1024 float4 per head
    int e4 = o4 & 1023;
    const float4* P = (const float4*)g_partial + h * CHUNKS * 1024 + e4;
    float4 sum = make_float4(0.f, 0.f, 0.f, 0.f);
    #pragma unroll
    for (int c = 0; c < CHUNKS; ++c) {
        float4 p = P[c * 1024];
        sum.x += p.x; sum.y += p.y; sum.z += p.z; sum.w += p.w;
    }
    ((float4*)g_M)[o4] = sum;
}

// ---------------------------------------------------------------------------
// Phase C: out = Q @ M.  Block: 64 q-rows x 64 cols, 16x16 threads, 4x4 tile.
// M rows read conflict-free (contiguous j), Q scalars broadcast + duplicated.
// ---------------------------------------------------------------------------
__global__ __launch_bounds__(256) void qm_kernel(
    const float* __restrict__ qg, float* __restrict__ outg)
{
    __shared__ float qs[DD * DD];   // 16 KB
    __shared__ float ms[DD * DD];   // 16 KB

    const int bx  = blockIdx.x;
    const int h   = bx >> 6;
    const int qt  = bx & 63;
    const int tid = threadIdx.x;
    const int ty  = tid >> 4;
    const int tx  = tid & 15;

    const float4* Qg = (const float4*)(qg + (h * SS + qt * 64) * DD);
    const float4* Mg = (const float4*)(g_M + h * 4096);
    float4* qs4 = (float4*)qs;
    float4* ms4 = (float4*)ms;

    #pragma unroll
    for (int it = 0; it < 4; ++it) {
        int o4 = tid + it * 256;
        qs4[o4] = Qg[o4];
        ms4[o4] = Mg[o4];
    }
    __syncthreads();

    const int i0 = ty * 4;
    unsigned long long acc[4][2];
    #pragma unroll
    for (int r = 0; r < 4; ++r) { acc[r][0] = 0ULL; acc[r][1] = 0ULL; }

    #pragma unroll 4
    for (int d4 = 0; d4 < 16; ++d4) {
        float4 qv[4];
        #pragma unroll
        for (int r = 0; r < 4; ++r)
            qv[r] = *(const float4*)&qs[(i0 + r) * DD + d4 * 4];   // broadcast
        #pragma unroll
        for (int dd = 0; dd < 4; ++dd) {
            ulonglong2 mv =
                *(const ulonglong2*)&ms[(d4 * 4 + dd) * DD + tx * 4]; // conflict-free
            #pragma unroll
            for (int r = 0; r < 4; ++r) {
                unsigned long long qd = dup2(((const float*)&qv[r])[dd]);
                FFMA2(acc[r][0], qd, mv.x);
                FFMA2(acc[r][1], qd, mv.y);
            }
        }
    }

    float* O = outg + (h * SS + qt * 64) * DD;
    #pragma unroll
    for (int r = 0; r < 4; ++r) {
        *(ulonglong2*)&O[(i0 + r) * DD + tx * 4] =
            make_ulonglong2(acc[r][0], acc[r][1]);
    }
}

// ---------------------------------------------------------------------------
extern "C" void kernel_launch(void* const* d_in, const int* in_sizes, int n_in,
                              void* d_out, int out_size)
{
    const float* q = (const float*)d_in[0];
    const float* k = (const float*)d_in[1];
    const float* v = (const float*)d_in[2];
    float* out = (float*)d_out;
    (void)in_sizes; (void)n_in; (void)out_size;

    ktv_partial_kernel<<<NH * CHUNKS, 256>>>(k, v);
    reduce_kernel<<<64, 256>>>();
    qm_kernel<<<NH * 64, 256>>>(q, out);
}